// round 6
// baseline (speedup 1.0000x reference)
#include <cuda_runtime.h>
#include <stdint.h>

// BasedKernel feature map, d=16:
//   out[row, 0]        = 1
//   out[row, 1..16]    = x[row, j-1] * 0.5
//   out[row, 17+idx]   = x[row, idx>>4] * x[row, idx&15] * SC2,  idx = 0..255
//
// R6: R5's 16-rows/512-threads scaling with the R5 deadlock fixed: R5 put a
// full-mask __shfl_sync inside a divergent `if (lane<17)` branch (hang). All
// shfls are now in convergent code; header is shfl-free (R4 form). Structure
// otherwise proven: one-value-per-lane x, hoisted-shfl quadratic, smem
// staging, single 1-D TMA bulk flush per block (L1-free output stream).

#define SC2 0.17677669529663687f

#define ROWS_PER_BLOCK 16
#define THREADS        512
#define FLOATS_PER_BLOCK (ROWS_PER_BLOCK * 273)      // 4368
#define BYTES_PER_BLOCK  (FLOATS_PER_BLOCK * 4)      // 17472, multiple of 16

__global__ void __launch_bounds__(THREADS, 4)
based_feature_kernel(const float* __restrict__ x,
                     float* __restrict__ out)
{
    __shared__ __align__(16) float buf[FLOATS_PER_BLOCK];

    const int tid  = threadIdx.x;
    const int warp = tid >> 5;                 // 0..15 = local row
    const int lane = tid & 31;
    const int row  = blockIdx.x * ROWS_PER_BLOCK + warp;

    // ---- Phase 1: one row per warp, x resident one-value-per-lane ----
    const float* xr = x + (size_t)row * 16;
    float v = (lane < 16) ? __ldg(xr + lane) : 0.0f;

    float* o = buf + warp * 273;

    // Convergent shfls first (full warp participates).
    const float b2 = __shfl_sync(0xffffffffu, v, lane & 15) * SC2;  // k-operand
    const int   hi = lane >> 4;                                     // 0 or 1

    // Header (shfl-free, predicated stores only):
    if (lane < 16) o[1 + lane] = v * 0.5f;
    if (lane == 16) o[0] = 1.0f;

    // Quadratic part: idx = 32m + lane, i = 2m + hi, k = lane&15.
#pragma unroll
    for (int m = 0; m < 8; ++m) {
        const float a = __shfl_sync(0xffffffffu, v, 2 * m + hi);
        o[17 + 32 * m + lane] = a * b2;
    }

    __syncthreads();

    // ---- Phase 2: single 1-D TMA bulk store smem -> gmem (bypasses L1) ----
    if (tid == 0) {
        uint32_t saddr;
        asm volatile(
            "{ .reg .u64 t; cvta.to.shared.u64 t, %1; cvt.u32.u64 %0, t; }"
            : "=r"(saddr) : "l"(buf));

        float* g = out + (size_t)blockIdx.x * FLOATS_PER_BLOCK;
        const int nbytes = BYTES_PER_BLOCK;

        asm volatile("fence.proxy.async.shared::cta;" ::: "memory");
        asm volatile(
            "cp.async.bulk.global.shared::cta.bulk_group [%0], [%1], %2;"
            :: "l"(g), "r"(saddr), "r"(nbytes) : "memory");
        asm volatile("cp.async.bulk.commit_group;" ::: "memory");
        asm volatile("cp.async.bulk.wait_group.read 0;" ::: "memory");
    }
}

extern "C" void kernel_launch(void* const* d_in, const int* in_sizes, int n_in,
                              void* d_out, int out_size)
{
    const float* x = (const float*)d_in[0];
    float* out = (float*)d_out;

    const int n_rows = in_sizes[0] / 16;              // 262144
    const int blocks = n_rows / ROWS_PER_BLOCK;       // 16384 (exact)

    based_feature_kernel<<<blocks, THREADS>>>(x, out);
}